// round 1
// baseline (speedup 1.0000x reference)
#include <cuda_runtime.h>
#include <math.h>

#define N 8192
#define CLS 8
#define DIM 256
#define INV_T 14.2857142857142857f   /* 1/0.07 */
#define ALPHA 0.3f
#define LSM 0.1f

// ---------------- scratch (persistent __device__ globals; every kernel overwrites) ----
__device__ float g_embn[N * DIM];          // normalized embeddings
__device__ float g_clsum_part[CLS * 8 * DIM];
__device__ float g_clcnt_part[CLS * 8];
__device__ float g_clsum[CLS * DIM];
__device__ float g_clcnt[CLS];
__device__ float g_rowZ[N * 4];            // per-row partial sums of exp(sim), 4 col-splits
__device__ float g_con[N];                 // per-row contrastive loss
__device__ float g_ce_part[32];            // per-block focal-CE partials

// ---------------- 1) normalize embeddings -------------------------------------------
__global__ void k_norm(const float* __restrict__ emb) {
    int row = blockIdx.x;
    int d = threadIdx.x;
    float v = emb[row * DIM + d];
    __shared__ float s[DIM];
    s[d] = v * v;
    __syncthreads();
    for (int off = DIM / 2; off > 0; off >>= 1) {
        if (d < off) s[d] += s[d + off];
        __syncthreads();
    }
    float norm = fmaxf(sqrtf(s[0]), 1e-12f);
    g_embn[row * DIM + d] = v / norm;
}

// ---------------- 2) class sums (partial, deterministic) ----------------------------
// blockIdx.x = c*8 + chunk ; each block scans 1024 rows for class c
__global__ void k_clspart(const int* __restrict__ tgt) {
    int c = blockIdx.x >> 3;
    int chunk = blockIdx.x & 7;
    int d = threadIdx.x;
    int i0 = chunk * 1024;
    __shared__ int st[1024];
    for (int k = d; k < 1024; k += 256) st[k] = tgt[i0 + k];
    __syncthreads();
    float a0 = 0.f, a1 = 0.f, a2 = 0.f, a3 = 0.f;
    int cnt = 0;
    for (int k = 0; k < 1024; k += 4) {
        int t0 = st[k], t1 = st[k + 1], t2 = st[k + 2], t3 = st[k + 3];
        if (t0 == c) a0 += g_embn[(i0 + k + 0) * DIM + d];
        if (t1 == c) a1 += g_embn[(i0 + k + 1) * DIM + d];
        if (t2 == c) a2 += g_embn[(i0 + k + 2) * DIM + d];
        if (t3 == c) a3 += g_embn[(i0 + k + 3) * DIM + d];
        if (d == 0) cnt += (t0 == c) + (t1 == c) + (t2 == c) + (t3 == c);
    }
    g_clsum_part[blockIdx.x * DIM + d] = (a0 + a1) + (a2 + a3);
    if (d == 0) g_clcnt_part[blockIdx.x] = (float)cnt;
}

__global__ void k_clsfinal() {
    int c = blockIdx.x;
    int d = threadIdx.x;
    float s = 0.f;
    for (int ch = 0; ch < 8; ch++) s += g_clsum_part[(c * 8 + ch) * DIM + d];
    g_clsum[c * DIM + d] = s;
    if (d == 0) {
        float cn = 0.f;
        for (int ch = 0; ch < 8; ch++) cn += g_clcnt_part[c * 8 + ch];
        g_clcnt[c] = cn;
    }
}

// ---------------- 3) focal cross-entropy (per-row, then block partial) ---------------
__global__ void k_ce(const float* __restrict__ logits, const int* __restrict__ tgt) {
    int i = blockIdx.x * 256 + threadIdx.x;
    const float4* p = (const float4*)(logits + i * CLS);
    float4 u = p[0], w = p[1];
    float x[CLS] = {u.x, u.y, u.z, u.w, w.x, w.y, w.z, w.w};
    float m = x[0];
#pragma unroll
    for (int j = 1; j < CLS; j++) m = fmaxf(m, x[j]);
    float se = 0.f;
#pragma unroll
    for (int j = 0; j < CLS; j++) se += expf(x[j] - m);
    float lse = m + logf(se);
    int t = tgt[i];
    float nll = lse - x[t];
    float sx = 0.f;
#pragma unroll
    for (int j = 0; j < CLS; j++) sx += x[j];
    float smooth = lse - sx * (1.0f / CLS);
    float ce = (1.0f - LSM) * nll + LSM * smooth;
    float pt = expf(-ce);
    float omp = 1.0f - pt;
    float focal = omp * omp * ce;

    __shared__ float s[256];
    s[threadIdx.x] = focal;
    __syncthreads();
    for (int off = 128; off > 0; off >>= 1) {
        if (threadIdx.x < off) s[threadIdx.x] += s[threadIdx.x + off];
        __syncthreads();
    }
    if (threadIdx.x == 0) g_ce_part[blockIdx.x] = s[0];
}

// ---------------- 4) the hot kernel: Z_i = sum_j exp(e_i.e_j / T) -------------------
// Tiled fp32 "GEMM + exp-rowsum". BM=BN=128, BK=16, 256 threads (16x16), 8x8 microtile.
// grid = (64 row-tiles, 4 column splits of 2048 cols each)
__global__ void __launch_bounds__(256) k_sim() {
    __shared__ float As[16][128];
    __shared__ float Bs[16][128];
    __shared__ float red[128][16];

    int tid = threadIdx.x;
    int tx = tid & 15, ty = tid >> 4;
    int r0 = blockIdx.x * 128;
    int csplit = blockIdx.y;

    float rs[8];
#pragma unroll
    for (int i = 0; i < 8; i++) rs[i] = 0.f;

    for (int ct = 0; ct < 16; ct++) {
        int c0 = csplit * 2048 + ct * 128;
        float acc[8][8];
#pragma unroll
        for (int i = 0; i < 8; i++)
#pragma unroll
            for (int j = 0; j < 8; j++) acc[i][j] = 0.f;

        for (int k0 = 0; k0 < DIM; k0 += 16) {
#pragma unroll
            for (int l = 0; l < 2; l++) {
                int f4 = tid * 2 + l;          // [0,512)
                int row = f4 >> 2;             // [0,128)
                int cq = f4 & 3;               // which float4 within the 16-wide chunk
                float4 v = *(const float4*)&g_embn[(r0 + row) * DIM + k0 + cq * 4];
                As[cq * 4 + 0][row] = v.x;
                As[cq * 4 + 1][row] = v.y;
                As[cq * 4 + 2][row] = v.z;
                As[cq * 4 + 3][row] = v.w;
                float4 wv = *(const float4*)&g_embn[(c0 + row) * DIM + k0 + cq * 4];
                Bs[cq * 4 + 0][row] = wv.x;
                Bs[cq * 4 + 1][row] = wv.y;
                Bs[cq * 4 + 2][row] = wv.z;
                Bs[cq * 4 + 3][row] = wv.w;
            }
            __syncthreads();
#pragma unroll
            for (int kk = 0; kk < 16; kk++) {
                float a[8], b[8];
                *(float4*)&a[0] = *(const float4*)&As[kk][ty * 8];
                *(float4*)&a[4] = *(const float4*)&As[kk][ty * 8 + 4];
                *(float4*)&b[0] = *(const float4*)&Bs[kk][tx * 8];
                *(float4*)&b[4] = *(const float4*)&Bs[kk][tx * 8 + 4];
#pragma unroll
                for (int i = 0; i < 8; i++)
#pragma unroll
                    for (int j = 0; j < 8; j++) acc[i][j] = fmaf(a[i], b[j], acc[i][j]);
            }
            __syncthreads();
        }
        // epilogue: exp and accumulate per-row
#pragma unroll
        for (int i = 0; i < 8; i++) {
            float s = 0.f;
#pragma unroll
            for (int j = 0; j < 8; j++) s += __expf(acc[i][j] * INV_T);
            rs[i] += s;
        }
    }

    // reduce rs across the 16 tx-threads per row (deterministic)
#pragma unroll
    for (int i = 0; i < 8; i++) red[ty * 8 + i][tx] = rs[i];
    __syncthreads();
    if (tid < 128) {
        float s = 0.f;
#pragma unroll
        for (int k = 0; k < 16; k++) s += red[tid][k];
        g_rowZ[(r0 + tid) * 4 + csplit] = s;
    }
}

// ---------------- 5) per-row contrastive loss ---------------------------------------
__global__ void k_con(const int* __restrict__ tgt) {
    int w = threadIdx.x >> 5, lane = threadIdx.x & 31;
    int row = blockIdx.x * 8 + w;
    int t = tgt[row];
    const float4* e = (const float4*)&g_embn[row * DIM];
    const float4* sc = (const float4*)&g_clsum[t * DIM];
    float dot = 0.f;
#pragma unroll
    for (int k = lane; k < DIM / 4; k += 32) {
        float4 a = e[k], b = sc[k];
        dot += a.x * b.x + a.y * b.y + a.z * b.z + a.w * b.w;
    }
#pragma unroll
    for (int off = 16; off > 0; off >>= 1) dot += __shfl_xor_sync(0xFFFFFFFF, dot, off);
    if (lane == 0) {
        float Z = (g_rowZ[row * 4 + 0] + g_rowZ[row * 4 + 1]) +
                  (g_rowZ[row * 4 + 2] + g_rowZ[row * 4 + 3]);
        float logZ = logf(Z + 1e-8f);
        float npos = g_clcnt[t] - 1.0f;
        float msum = (dot - 1.0f) * INV_T;  // e_i.e_i == 1 (unit norm)
        g_con[row] = (npos * logZ - msum) / fmaxf(npos, 1.0f);
    }
}

// ---------------- 6) final deterministic reduction ----------------------------------
__global__ void k_final(float* __restrict__ out, int out_size) {
    __shared__ float s[256];
    int t = threadIdx.x;

    float cs = 0.f;
    for (int i = t; i < N; i += 256) cs += g_con[i];
    s[t] = cs;
    __syncthreads();
    for (int off = 128; off > 0; off >>= 1) {
        if (t < off) s[t] += s[t + off];
        __syncthreads();
    }
    __shared__ float con_sum;
    if (t == 0) con_sum = s[0];
    __syncthreads();

    s[t] = (t < 32) ? g_ce_part[t] : 0.f;
    __syncthreads();
    for (int off = 128; off > 0; off >>= 1) {
        if (t < off) s[t] += s[t + off];
        __syncthreads();
    }
    if (t == 0) {
        float ce_mean = s[0] * (1.0f / N);
        float con_mean = con_sum * (1.0f / N);
        float total = ce_mean + ALPHA * con_mean;
        out[0] = total;
        if (out_size > 1) out[1] = ce_mean;
        if (out_size > 2) out[2] = con_mean;
    }
}

// ---------------- launcher ----------------------------------------------------------
extern "C" void kernel_launch(void* const* d_in, const int* in_sizes, int n_in,
                              void* d_out, int out_size) {
    const float* logits = (const float*)d_in[0];
    const float* emb = (const float*)d_in[1];
    const int* tgt = (const int*)d_in[2];
    float* out = (float*)d_out;

    k_norm<<<N, DIM>>>(emb);
    k_clspart<<<CLS * 8, 256>>>(tgt);
    k_clsfinal<<<CLS, DIM>>>();
    k_ce<<<N / 256, 256>>>(logits, tgt);
    k_sim<<<dim3(N / 128, 4), 256>>>();
    k_con<<<N / 8, 256>>>(tgt);
    k_final<<<1, 256>>>(out, out_size);
}

// round 3
// speedup vs baseline: 4.7943x; 4.7943x over previous
#include <cuda_runtime.h>
#include <cuda_bf16.h>
#include <math.h>
#include <stdint.h>

#define N 8192
#define CLS 8
#define DIM 256
#define INV_T 14.285714285714286f
#define EXP_SCALE 20.60992915555662f   /* (1/0.07) * log2(e) */
#define ALPHA 0.3f
#define LSM 0.1f

// ---------------- scratch (__device__ globals; fully overwritten every launch) -------
__device__ float g_embn[N * DIM];
__device__ __nv_bfloat16 g_embh[N * DIM];
__device__ float g_clsum_part[32 * CLS * DIM];
__device__ float g_clcnt_part[32 * CLS];
__device__ float g_clsum[CLS * DIM];
__device__ float g_clcnt[CLS];
__device__ float g_rowZ[N * 2];
__device__ float g_con[N];
__device__ float g_ce_part[32];

// ---------------- helpers ------------------------------------------------------------
__device__ __forceinline__ uint32_t smem_u32(const void* p) {
    uint32_t a;
    asm("{ .reg .u64 t; cvta.to.shared.u64 t, %1; cvt.u32.u64 %0, t; }" : "=r"(a) : "l"(p));
    return a;
}
__device__ __forceinline__ float ex2f(float x) {
    float y; asm("ex2.approx.f32 %0, %1;" : "=f"(y) : "f"(x)); return y;
}
__device__ __forceinline__ void cp16(uint32_t dst, const void* src) {
    asm volatile("cp.async.cg.shared.global [%0], [%1], 16;" :: "r"(dst), "l"(src));
}
#define CP_COMMIT() asm volatile("cp.async.commit_group;" ::: "memory")
#define CP_WAIT0()  asm volatile("cp.async.wait_group 0;" ::: "memory")

__device__ __forceinline__ void ldsm4(uint32_t& r0, uint32_t& r1, uint32_t& r2, uint32_t& r3,
                                      uint32_t addr) {
    asm volatile("ldmatrix.sync.aligned.m8n8.x4.shared.b16 {%0,%1,%2,%3}, [%4];"
                 : "=r"(r0), "=r"(r1), "=r"(r2), "=r"(r3) : "r"(addr));
}
__device__ __forceinline__ void mma_bf16(float* c, uint32_t a0, uint32_t a1, uint32_t a2,
                                         uint32_t a3, uint32_t b0, uint32_t b1) {
    asm volatile("mma.sync.aligned.m16n8k16.row.col.f32.bf16.bf16.f32 "
                 "{%0,%1,%2,%3}, {%4,%5,%6,%7}, {%8,%9}, {%0,%1,%2,%3};"
                 : "+f"(c[0]), "+f"(c[1]), "+f"(c[2]), "+f"(c[3])
                 : "r"(a0), "r"(a1), "r"(a2), "r"(a3), "r"(b0), "r"(b1));
}

// ---------------- 1) normalize + bf16 convert ---------------------------------------
__global__ void k_norm(const float* __restrict__ emb) {
    int row = blockIdx.x;
    int d = threadIdx.x;
    float v = emb[row * DIM + d];
    __shared__ float s[DIM];
    s[d] = v * v;
    __syncthreads();
    for (int off = DIM / 2; off > 0; off >>= 1) {
        if (d < off) s[d] += s[d + off];
        __syncthreads();
    }
    float norm = fmaxf(sqrtf(s[0]), 1e-12f);
    float nv = v / norm;
    g_embn[row * DIM + d] = nv;
    g_embh[row * DIM + d] = __float2bfloat16(nv);
}

// ---------------- 2) class sums ------------------------------------------------------
__global__ void k_clspart(const int* __restrict__ tgt) {
    int b = blockIdx.x, d = threadIdx.x;
    int i0 = b * 256;
    __shared__ int st[256];
    st[d] = tgt[i0 + d];
    __syncthreads();
    float a[CLS];
#pragma unroll
    for (int c = 0; c < CLS; c++) a[c] = 0.f;
    for (int k = 0; k < 256; k++) {
        float v = g_embn[(i0 + k) * DIM + d];
        int t = st[k];
#pragma unroll
        for (int c = 0; c < CLS; c++) a[c] += (t == c) ? v : 0.f;
    }
#pragma unroll
    for (int c = 0; c < CLS; c++) g_clsum_part[(b * CLS + c) * DIM + d] = a[c];
    if (d == 0) {
        int cnt[CLS];
#pragma unroll
        for (int c = 0; c < CLS; c++) cnt[c] = 0;
        for (int k = 0; k < 256; k++) {
#pragma unroll
            for (int c = 0; c < CLS; c++) cnt[c] += (st[k] == c);
        }
#pragma unroll
        for (int c = 0; c < CLS; c++) g_clcnt_part[b * CLS + c] = (float)cnt[c];
    }
}

__global__ void k_clsfinal() {
    int c = blockIdx.x, d = threadIdx.x;
    float s = 0.f;
    for (int b = 0; b < 32; b++) s += g_clsum_part[(b * CLS + c) * DIM + d];
    g_clsum[c * DIM + d] = s;
    if (d == 0) {
        float cn = 0.f;
        for (int b = 0; b < 32; b++) cn += g_clcnt_part[b * CLS + c];
        g_clcnt[c] = cn;
    }
}

// ---------------- 3) focal cross-entropy --------------------------------------------
__global__ void k_ce(const float* __restrict__ logits, const int* __restrict__ tgt) {
    int i = blockIdx.x * 256 + threadIdx.x;
    const float4* p = (const float4*)(logits + i * CLS);
    float4 u = p[0], w = p[1];
    float x[CLS] = {u.x, u.y, u.z, u.w, w.x, w.y, w.z, w.w};
    float m = x[0];
#pragma unroll
    for (int j = 1; j < CLS; j++) m = fmaxf(m, x[j]);
    float se = 0.f;
#pragma unroll
    for (int j = 0; j < CLS; j++) se += expf(x[j] - m);
    float lse = m + logf(se);
    int t = tgt[i];
    float nll = lse - x[t];
    float sx = 0.f;
#pragma unroll
    for (int j = 0; j < CLS; j++) sx += x[j];
    float smooth = lse - sx * (1.0f / CLS);
    float ce = (1.0f - LSM) * nll + LSM * smooth;
    float pt = expf(-ce);
    float omp = 1.0f - pt;
    float focal = omp * omp * ce;

    __shared__ float s[256];
    s[threadIdx.x] = focal;
    __syncthreads();
    for (int off = 128; off > 0; off >>= 1) {
        if (threadIdx.x < off) s[threadIdx.x] += s[threadIdx.x + off];
        __syncthreads();
    }
    if (threadIdx.x == 0) g_ce_part[blockIdx.x] = s[0];
}

// ---------------- 4) HOT: Z_i via mma.sync bf16 GEMM + exp-rowsum --------------------
// grid (64 row-tiles, 2 col-splits), 256 thr = 8 warps (4 My x 2 Nx), warp tile 32x64.
// A tile 128x256 resident in smem; 32 B tiles of 128x256 double-buffered via cp.async.
#define SA 264                      /* padded row stride in bf16 (+16B) */
#define A_BYTES (128 * SA * 2)      /* 67584 */
#define AS_OFF 0
#define BS_OFF(b) (A_BYTES + (b) * A_BYTES)
#define SMEM_TOTAL (3 * A_BYTES)

__device__ __forceinline__ void load_tile_async(uint32_t sbase, int grow0, int tid) {
    const char* src = (const char*)g_embh + (size_t)grow0 * 512;
#pragma unroll
    for (int i = 0; i < 16; i++) {
        int idx = tid + i * 256;
        int row = idx >> 5, cb = idx & 31;
        cp16(sbase + row * (SA * 2) + cb * 16, src + (size_t)row * 512 + cb * 16);
    }
}

__global__ void __launch_bounds__(256, 1) k_sim_mma() {
    extern __shared__ char smem[];
    uint32_t sb = smem_u32(smem);
    int tid = threadIdx.x;
    int lane = tid & 31;
    int wid = tid >> 5;
    int wx = wid & 1;          // N dir (2)
    int wy = wid >> 1;         // M dir (4)
    int r0 = blockIdx.x * 128;
    int cbase = blockIdx.y * 4096;

    // preload A + B0
    load_tile_async(sb + AS_OFF, r0, tid);
    load_tile_async(sb + BS_OFF(0), cbase, tid);
    CP_COMMIT();
    CP_WAIT0();
    __syncthreads();

    // ldmatrix base addresses (per-lane)
    // A (x4, 16x16): rows = wy*32 + mt*16 + (lane&15), col byte = (k0 + ((lane>>4)<<3))*2
    uint32_t a_addr = sb + AS_OFF + (wy * 32 + (lane & 15)) * (SA * 2) + ((lane >> 4) << 4);
    // B (x4 = two n-tiles): rows = n0 + (lane&7) + ((lane>>4)<<3), col = k0 + (((lane>>3)&1)<<3)
    uint32_t b_addr = sb + ((lane & 7) + ((lane >> 4) << 3)) * (SA * 2) + (((lane >> 3) & 1) << 4);
    uint32_t b_base = b_addr + (wx * 64) * (SA * 2);

    float rs[2][2] = {{0.f, 0.f}, {0.f, 0.f}};
    const float EXP_DIAG = expf(INV_T);
    int gr_lo0 = r0 + wy * 32 + (lane >> 2);      // mt=0 row_lo
    int colb = cbase + wx * 64 + (lane & 3) * 2;  // per-tile col = colb + t*128 + nt*8

    for (int ct = 0; ct < 32; ct++) {
        int buf = ct & 1;
        if (ct + 1 < 32) {
            load_tile_async(sb + BS_OFF(buf ^ 1), cbase + (ct + 1) * 128, tid);
            CP_COMMIT();
        }

        float acc[2][8][4];
#pragma unroll
        for (int mt = 0; mt < 2; mt++)
#pragma unroll
            for (int nt = 0; nt < 8; nt++)
#pragma unroll
                for (int q = 0; q < 4; q++) acc[mt][nt][q] = 0.f;

        uint32_t bbuf = b_base + BS_OFF(buf);
#pragma unroll
        for (int ks = 0; ks < 16; ks++) {
            uint32_t koff = ks * 32;  // 16 bf16 = 32 bytes
            uint32_t a0[4], a1[4];
            ldsm4(a0[0], a0[1], a0[2], a0[3], a_addr + koff);
            ldsm4(a1[0], a1[1], a1[2], a1[3], a_addr + 16 * (SA * 2) + koff);
            uint32_t bfr[4][4];
#pragma unroll
            for (int p = 0; p < 4; p++)
                ldsm4(bfr[p][0], bfr[p][1], bfr[p][2], bfr[p][3],
                      bbuf + (p * 16) * (SA * 2) + koff);
#pragma unroll
            for (int nt = 0; nt < 8; nt++) {
                uint32_t bb0 = bfr[nt >> 1][(nt & 1) * 2];
                uint32_t bb1 = bfr[nt >> 1][(nt & 1) * 2 + 1];
                mma_bf16(acc[0][nt], a0[0], a0[1], a0[2], a0[3], bb0, bb1);
                mma_bf16(acc[1][nt], a1[0], a1[1], a1[2], a1[3], bb0, bb1);
            }
        }

        // epilogue: exp + row-sum (exact diagonal)
        int ctcol = colb + ct * 128;
#pragma unroll
        for (int mt = 0; mt < 2; mt++) {
            int grl = gr_lo0 + mt * 16;
            int grh = grl + 8;
            float slo = 0.f, shi = 0.f;
#pragma unroll
            for (int nt = 0; nt < 8; nt++) {
                int gc = ctcol + nt * 8;
                float v0 = (gc == grl)     ? EXP_DIAG : ex2f(acc[mt][nt][0] * EXP_SCALE);
                float v1 = (gc + 1 == grl) ? EXP_DIAG : ex2f(acc[mt][nt][1] * EXP_SCALE);
                float v2 = (gc == grh)     ? EXP_DIAG : ex2f(acc[mt][nt][2] * EXP_SCALE);
                float v3 = (gc + 1 == grh) ? EXP_DIAG : ex2f(acc[mt][nt][3] * EXP_SCALE);
                slo += v0 + v1;
                shi += v2 + v3;
            }
            rs[mt][0] += slo;
            rs[mt][1] += shi;
        }

        if (ct + 1 < 32) CP_WAIT0();
        __syncthreads();
    }

    // reduce across the 4 lanes sharing a row, then across wx pair via smem
    float* red = (float*)smem;  // [128][2]
#pragma unroll
    for (int mt = 0; mt < 2; mt++)
#pragma unroll
        for (int h = 0; h < 2; h++) {
            float s = rs[mt][h];
            s += __shfl_xor_sync(0xFFFFFFFF, s, 1);
            s += __shfl_xor_sync(0xFFFFFFFF, s, 2);
            rs[mt][h] = s;
        }
    __syncthreads();   // done with As region before reuse
    if ((lane & 3) == 0) {
#pragma unroll
        for (int mt = 0; mt < 2; mt++)
#pragma unroll
            for (int h = 0; h < 2; h++) {
                int row = wy * 32 + mt * 16 + h * 8 + (lane >> 2);
                red[row * 2 + wx] = rs[mt][h];
            }
    }
    __syncthreads();
    if (tid < 128) {
        g_rowZ[(size_t)(r0 + tid) * 2 + blockIdx.y] = red[tid * 2] + red[tid * 2 + 1];
    }
}

// ---------------- 5) per-row contrastive loss ---------------------------------------
__global__ void k_con(const int* __restrict__ tgt) {
    int w = threadIdx.x >> 5, lane = threadIdx.x & 31;
    int row = blockIdx.x * 8 + w;
    int t = tgt[row];
    const float4* e = (const float4*)&g_embn[row * DIM];
    const float4* sc = (const float4*)&g_clsum[t * DIM];
    float dot = 0.f;
#pragma unroll
    for (int k = lane; k < DIM / 4; k += 32) {
        float4 a = e[k], b = sc[k];
        dot += a.x * b.x + a.y * b.y + a.z * b.z + a.w * b.w;
    }
#pragma unroll
    for (int off = 16; off > 0; off >>= 1) dot += __shfl_xor_sync(0xFFFFFFFF, dot, off);
    if (lane == 0) {
        float Z = g_rowZ[row * 2 + 0] + g_rowZ[row * 2 + 1];
        float logZ = logf(Z + 1e-8f);
        float npos = g_clcnt[t] - 1.0f;
        float msum = (dot - 1.0f) * INV_T;
        g_con[row] = (npos * logZ - msum) / fmaxf(npos, 1.0f);
    }
}

// ---------------- 6) final reduction -------------------------------------------------
__global__ void k_final(float* __restrict__ out, int out_size) {
    __shared__ float s[256];
    int t = threadIdx.x;

    float cs = 0.f;
    for (int i = t; i < N; i += 256) cs += g_con[i];
    s[t] = cs;
    __syncthreads();
    for (int off = 128; off > 0; off >>= 1) {
        if (t < off) s[t] += s[t + off];
        __syncthreads();
    }
    __shared__ float con_sum;
    if (t == 0) con_sum = s[0];
    __syncthreads();

    s[t] = (t < 32) ? g_ce_part[t] : 0.f;
    __syncthreads();
    for (int off = 128; off > 0; off >>= 1) {
        if (t < off) s[t] += s[t + off];
        __syncthreads();
    }
    if (t == 0) {
        float ce_mean = s[0] * (1.0f / N);
        float con_mean = con_sum * (1.0f / N);
        out[0] = ce_mean + ALPHA * con_mean;
        if (out_size > 1) out[1] = ce_mean;
        if (out_size > 2) out[2] = con_mean;
    }
}

// ---------------- launcher ----------------------------------------------------------
extern "C" void kernel_launch(void* const* d_in, const int* in_sizes, int n_in,
                              void* d_out, int out_size) {
    const float* logits = (const float*)d_in[0];
    const float* emb = (const float*)d_in[1];
    const int* tgt = (const int*)d_in[2];
    float* out = (float*)d_out;

    cudaFuncSetAttribute(k_sim_mma, cudaFuncAttributeMaxDynamicSharedMemorySize, SMEM_TOTAL);

    k_norm<<<N, DIM>>>(emb);
    k_clspart<<<32, 256>>>(tgt);
    k_clsfinal<<<CLS, DIM>>>();
    k_ce<<<N / 256, 256>>>(logits, tgt);
    k_sim_mma<<<dim3(64, 2), 256, SMEM_TOTAL>>>();
    k_con<<<N / 8, 256>>>(tgt);
    k_final<<<1, 256>>>(out, out_size);
}

// round 4
// speedup vs baseline: 6.9781x; 1.4555x over previous
#include <cuda_runtime.h>
#include <cuda_bf16.h>
#include <math.h>
#include <stdint.h>

#define N 8192
#define CLS 8
#define DIM 256
#define INV_T 14.285714285714286f
#define EXP_SCALE 20.60992915555662f   /* (1/0.07) * log2(e) */
#define ALPHA 0.3f
#define LSM 0.1f
#define NT_ROW 64                      /* 64 row tiles of 128 */

// ---------------- scratch (__device__ globals; fully overwritten every launch) -------
__device__ float g_embn[N * DIM];
__device__ __nv_bfloat16 g_embh[N * DIM];
__device__ float g_clsum_part[32 * CLS * DIM];
__device__ float g_clcnt_part[32 * CLS];
__device__ float g_clsum[CLS * DIM];
__device__ float g_clcnt[CLS];
__device__ float g_Zp[N * NT_ROW];     // Z partials: row x other-tile slot (each written once)
__device__ float g_con[N];
__device__ float g_ce_part[32];

// ---------------- helpers ------------------------------------------------------------
__device__ __forceinline__ uint32_t smem_u32(const void* p) {
    uint32_t a;
    asm("{ .reg .u64 t; cvta.to.shared.u64 t, %1; cvt.u32.u64 %0, t; }" : "=r"(a) : "l"(p));
    return a;
}
__device__ __forceinline__ float ex2f(float x) {
    float y; asm("ex2.approx.f32 %0, %1;" : "=f"(y) : "f"(x)); return y;
}
__device__ __forceinline__ void cp16(uint32_t dst, const void* src) {
    asm volatile("cp.async.cg.shared.global [%0], [%1], 16;" :: "r"(dst), "l"(src));
}
#define CP_COMMIT() asm volatile("cp.async.commit_group;" ::: "memory")
#define CP_WAIT0()  asm volatile("cp.async.wait_group 0;" ::: "memory")

__device__ __forceinline__ void ldsm4(uint32_t& r0, uint32_t& r1, uint32_t& r2, uint32_t& r3,
                                      uint32_t addr) {
    asm volatile("ldmatrix.sync.aligned.m8n8.x4.shared.b16 {%0,%1,%2,%3}, [%4];"
                 : "=r"(r0), "=r"(r1), "=r"(r2), "=r"(r3) : "r"(addr));
}
__device__ __forceinline__ void mma_bf16(float* c, uint32_t a0, uint32_t a1, uint32_t a2,
                                         uint32_t a3, uint32_t b0, uint32_t b1) {
    asm volatile("mma.sync.aligned.m16n8k16.row.col.f32.bf16.bf16.f32 "
                 "{%0,%1,%2,%3}, {%4,%5,%6,%7}, {%8,%9}, {%0,%1,%2,%3};"
                 : "+f"(c[0]), "+f"(c[1]), "+f"(c[2]), "+f"(c[3])
                 : "r"(a0), "r"(a1), "r"(a2), "r"(a3), "r"(b0), "r"(b1));
}

// ---------------- 1) normalize + bf16 convert ---------------------------------------
__global__ void k_norm(const float* __restrict__ emb) {
    int row = blockIdx.x;
    int d = threadIdx.x;
    float v = emb[row * DIM + d];
    __shared__ float s[DIM];
    s[d] = v * v;
    __syncthreads();
    for (int off = DIM / 2; off > 0; off >>= 1) {
        if (d < off) s[d] += s[d + off];
        __syncthreads();
    }
    float norm = fmaxf(sqrtf(s[0]), 1e-12f);
    float nv = v / norm;
    g_embn[row * DIM + d] = nv;
    g_embh[row * DIM + d] = __float2bfloat16(nv);
}

// ---------------- 2) class sums ------------------------------------------------------
__global__ void k_clspart(const int* __restrict__ tgt) {
    int b = blockIdx.x, d = threadIdx.x;
    int i0 = b * 256;
    __shared__ int st[256];
    st[d] = tgt[i0 + d];
    __syncthreads();
    float a[CLS];
#pragma unroll
    for (int c = 0; c < CLS; c++) a[c] = 0.f;
    for (int k = 0; k < 256; k++) {
        float v = g_embn[(i0 + k) * DIM + d];
        int t = st[k];
#pragma unroll
        for (int c = 0; c < CLS; c++) a[c] += (t == c) ? v : 0.f;
    }
#pragma unroll
    for (int c = 0; c < CLS; c++) g_clsum_part[(b * CLS + c) * DIM + d] = a[c];
    if (d == 0) {
        int cnt[CLS];
#pragma unroll
        for (int c = 0; c < CLS; c++) cnt[c] = 0;
        for (int k = 0; k < 256; k++) {
#pragma unroll
            for (int c = 0; c < CLS; c++) cnt[c] += (st[k] == c);
        }
#pragma unroll
        for (int c = 0; c < CLS; c++) g_clcnt_part[b * CLS + c] = (float)cnt[c];
    }
}

__global__ void k_clsfinal() {
    int c = blockIdx.x, d = threadIdx.x;
    float s = 0.f;
    for (int b = 0; b < 32; b++) s += g_clsum_part[(b * CLS + c) * DIM + d];
    g_clsum[c * DIM + d] = s;
    if (d == 0) {
        float cn = 0.f;
        for (int b = 0; b < 32; b++) cn += g_clcnt_part[b * CLS + c];
        g_clcnt[c] = cn;
    }
}

// ---------------- 3) focal cross-entropy --------------------------------------------
__global__ void k_ce(const float* __restrict__ logits, const int* __restrict__ tgt) {
    int i = blockIdx.x * 256 + threadIdx.x;
    const float4* p = (const float4*)(logits + i * CLS);
    float4 u = p[0], w = p[1];
    float x[CLS] = {u.x, u.y, u.z, u.w, w.x, w.y, w.z, w.w};
    float m = x[0];
#pragma unroll
    for (int j = 1; j < CLS; j++) m = fmaxf(m, x[j]);
    float se = 0.f;
#pragma unroll
    for (int j = 0; j < CLS; j++) se += expf(x[j] - m);
    float lse = m + logf(se);
    int t = tgt[i];
    float nll = lse - x[t];
    float sx = 0.f;
#pragma unroll
    for (int j = 0; j < CLS; j++) sx += x[j];
    float smooth = lse - sx * (1.0f / CLS);
    float ce = (1.0f - LSM) * nll + LSM * smooth;
    float pt = expf(-ce);
    float omp = 1.0f - pt;
    float focal = omp * omp * ce;

    __shared__ float s[256];
    s[threadIdx.x] = focal;
    __syncthreads();
    for (int off = 128; off > 0; off >>= 1) {
        if (threadIdx.x < off) s[threadIdx.x] += s[threadIdx.x + off];
        __syncthreads();
    }
    if (threadIdx.x == 0) g_ce_part[blockIdx.x] = s[0];
}

// ---------------- 4) HOT: symmetric Z via mma.sync bf16 -----------------------------
// Upper-triangle tile enumeration: 2080 tiles of 128x128, 130 CTAs x 16 tiles.
// A tile resident (reloaded on row-tile change), B double-buffered cp.async.
// Each tile credits rowsums (slot J of rows in tile I) and colsums (slot I of rows
// in tile J, I<J).
#define SA 264
#define A_BYTES (128 * SA * 2)         /* 67584 */
#define AS_OFF 0
#define BS_OFF(b) (A_BYTES + (b) * A_BYTES)
#define RED_OFF (3 * A_BYTES)          /* 202752 */
#define SMEM_TOTAL (RED_OFF + 128 * 2 * 4 + 128 * 4 * 4)

__device__ __forceinline__ void load_tile_async(uint32_t sbase, int grow0, int tid) {
    const char* src = (const char*)g_embh + (size_t)grow0 * 512;
#pragma unroll
    for (int i = 0; i < 16; i++) {
        int idx = tid + i * 256;
        int row = idx >> 5, cb = idx & 31;
        cp16(sbase + row * (SA * 2) + cb * 16, src + (size_t)row * 512 + cb * 16);
    }
}

__global__ void __launch_bounds__(256, 1) k_sim_sym() {
    extern __shared__ char smem[];
    uint32_t sb = smem_u32(smem);
    float* red_row = (float*)(smem + RED_OFF);          // [128][2]
    float* red_col = (float*)(smem + RED_OFF + 1024);   // [128][4]
    int tid = threadIdx.x;
    int lane = tid & 31;
    int wid = tid >> 5;
    int wx = wid & 1;
    int wy = wid >> 1;

    // decode first tile (I,J) of this CTA's run of 16
    int rem = blockIdx.x * 16;
    int I = 0;
    while (rem >= NT_ROW - I) { rem -= NT_ROW - I; I++; }
    int J = I + rem;

    // per-lane ldmatrix bases
    uint32_t a_addr = sb + AS_OFF + (wy * 32 + (lane & 15)) * (SA * 2) + ((lane >> 4) << 4);
    uint32_t b_addr = sb + ((lane & 7) + ((lane >> 4) << 3)) * (SA * 2) + (((lane >> 3) & 1) << 4);
    uint32_t b_base = b_addr + (wx * 64) * (SA * 2);

    const float EXP_DIAG = expf(INV_T);
    int lrl0 = wy * 32 + (lane >> 2);          // local row (mt=0, lo half)
    int lcb0 = wx * 64 + (lane & 3) * 2;       // local col base (nt=0)

    int curI = -1;

    for (int k = 0; k < 16; k++) {
        int buf = k & 1;
        if (I != curI) {
            load_tile_async(sb + AS_OFF, I * 128, tid);
            if (k == 0) load_tile_async(sb + BS_OFF(0), J * 128, tid);
            CP_COMMIT();
            CP_WAIT0();
            __syncthreads();
            curI = I;
        }
        // prefetch next tile's B
        int I1 = I, J1 = J + 1;
        if (J1 == NT_ROW) { I1 = I + 1; J1 = I1; }
        if (k + 1 < 16) {
            load_tile_async(sb + BS_OFF(buf ^ 1), J1 * 128, tid);
            CP_COMMIT();
        }

        // ---- MMA: 128x128x256 ----
        float acc[2][8][4];
#pragma unroll
        for (int mt = 0; mt < 2; mt++)
#pragma unroll
            for (int nt = 0; nt < 8; nt++)
#pragma unroll
                for (int q = 0; q < 4; q++) acc[mt][nt][q] = 0.f;

        uint32_t bbuf = b_base + BS_OFF(buf);
#pragma unroll
        for (int ks = 0; ks < 16; ks++) {
            uint32_t koff = ks * 32;
            uint32_t a0[4], a1[4];
            ldsm4(a0[0], a0[1], a0[2], a0[3], a_addr + koff);
            ldsm4(a1[0], a1[1], a1[2], a1[3], a_addr + 16 * (SA * 2) + koff);
            uint32_t bfr[4][4];
#pragma unroll
            for (int p = 0; p < 4; p++)
                ldsm4(bfr[p][0], bfr[p][1], bfr[p][2], bfr[p][3],
                      bbuf + (p * 16) * (SA * 2) + koff);
#pragma unroll
            for (int nt = 0; nt < 8; nt++) {
                uint32_t bb0 = bfr[nt >> 1][(nt & 1) * 2];
                uint32_t bb1 = bfr[nt >> 1][(nt & 1) * 2 + 1];
                mma_bf16(acc[0][nt], a0[0], a0[1], a0[2], a0[3], bb0, bb1);
                mma_bf16(acc[1][nt], a1[0], a1[1], a1[2], a1[3], bb0, bb1);
            }
        }

        // ---- epilogue: exp (exact diagonal), row sums + col sums ----
        bool dt = (I == J);
        float ev[2][8][4];
#pragma unroll
        for (int mt = 0; mt < 2; mt++) {
            int lr = lrl0 + mt * 16;
#pragma unroll
            for (int nt = 0; nt < 8; nt++) {
                int lc = lcb0 + nt * 8;
                ev[mt][nt][0] = (dt && lc == lr)         ? EXP_DIAG : ex2f(acc[mt][nt][0] * EXP_SCALE);
                ev[mt][nt][1] = (dt && lc + 1 == lr)     ? EXP_DIAG : ex2f(acc[mt][nt][1] * EXP_SCALE);
                ev[mt][nt][2] = (dt && lc == lr + 8)     ? EXP_DIAG : ex2f(acc[mt][nt][2] * EXP_SCALE);
                ev[mt][nt][3] = (dt && lc + 1 == lr + 8) ? EXP_DIAG : ex2f(acc[mt][nt][3] * EXP_SCALE);
            }
        }

        // row sums: reduce over nt in-thread, then lane&3 quad
        float rlo[2], rhi[2];
#pragma unroll
        for (int mt = 0; mt < 2; mt++) {
            float sl = 0.f, sh = 0.f;
#pragma unroll
            for (int nt = 0; nt < 8; nt++) {
                sl += ev[mt][nt][0] + ev[mt][nt][1];
                sh += ev[mt][nt][2] + ev[mt][nt][3];
            }
            sl += __shfl_xor_sync(0xFFFFFFFF, sl, 1);
            sl += __shfl_xor_sync(0xFFFFFFFF, sl, 2);
            sh += __shfl_xor_sync(0xFFFFFFFF, sh, 1);
            sh += __shfl_xor_sync(0xFFFFFFFF, sh, 2);
            rlo[mt] = sl; rhi[mt] = sh;
        }

        // col sums: reduce over mt + row-halves in-thread, then lane>>2 groups
        float cp0[8], cp1[8];
#pragma unroll
        for (int nt = 0; nt < 8; nt++) {
            float c0 = (ev[0][nt][0] + ev[0][nt][2]) + (ev[1][nt][0] + ev[1][nt][2]);
            float c1 = (ev[0][nt][1] + ev[0][nt][3]) + (ev[1][nt][1] + ev[1][nt][3]);
            c0 += __shfl_xor_sync(0xFFFFFFFF, c0, 4);
            c0 += __shfl_xor_sync(0xFFFFFFFF, c0, 8);
            c0 += __shfl_xor_sync(0xFFFFFFFF, c0, 16);
            c1 += __shfl_xor_sync(0xFFFFFFFF, c1, 4);
            c1 += __shfl_xor_sync(0xFFFFFFFF, c1, 8);
            c1 += __shfl_xor_sync(0xFFFFFFFF, c1, 16);
            cp0[nt] = c0; cp1[nt] = c1;
        }

        // stage in smem
        if ((lane & 3) == 0) {
#pragma unroll
            for (int mt = 0; mt < 2; mt++) {
                int r = wy * 32 + mt * 16 + (lane >> 2);
                red_row[r * 2 + wx] = rlo[mt];
                red_row[(r + 8) * 2 + wx] = rhi[mt];
            }
        }
        if (lane < 4) {
#pragma unroll
            for (int nt = 0; nt < 8; nt++) {
                int c = wx * 64 + nt * 8 + lane * 2;
                red_col[c * 4 + wy] = cp0[nt];
                red_col[(c + 1) * 4 + wy] = cp1[nt];
            }
        }
        __syncthreads();
        if (tid < 128) {
            float rz = red_row[tid * 2] + red_row[tid * 2 + 1];
            g_Zp[(size_t)(I * 128 + tid) * NT_ROW + J] = rz;
            if (!dt) {
                float cz = (red_col[tid * 4] + red_col[tid * 4 + 1]) +
                           (red_col[tid * 4 + 2] + red_col[tid * 4 + 3]);
                g_Zp[(size_t)(J * 128 + tid) * NT_ROW + I] = cz;
            }
        }
        CP_WAIT0();
        __syncthreads();

        I = I1; J = J1;
    }
}

// ---------------- 5) per-row contrastive loss (reduce Z partials too) ----------------
__global__ void k_con(const int* __restrict__ tgt) {
    int w = threadIdx.x >> 5, lane = threadIdx.x & 31;
    int row = blockIdx.x * 8 + w;
    int t = tgt[row];
    float zs = g_Zp[(size_t)row * NT_ROW + lane] + g_Zp[(size_t)row * NT_ROW + lane + 32];
    const float4* e = (const float4*)&g_embn[row * DIM];
    const float4* sc = (const float4*)&g_clsum[t * DIM];
    float dot = 0.f;
#pragma unroll
    for (int k = lane; k < DIM / 4; k += 32) {
        float4 a = e[k], b = sc[k];
        dot += a.x * b.x + a.y * b.y + a.z * b.z + a.w * b.w;
    }
#pragma unroll
    for (int off = 16; off > 0; off >>= 1) {
        dot += __shfl_xor_sync(0xFFFFFFFF, dot, off);
        zs += __shfl_xor_sync(0xFFFFFFFF, zs, off);
    }
    if (lane == 0) {
        float logZ = logf(zs + 1e-8f);
        float npos = g_clcnt[t] - 1.0f;
        float msum = (dot - 1.0f) * INV_T;
        g_con[row] = (npos * logZ - msum) / fmaxf(npos, 1.0f);
    }
}

// ---------------- 6) final reduction -------------------------------------------------
__global__ void k_final(float* __restrict__ out, int out_size) {
    __shared__ float s[256];
    int t = threadIdx.x;

    float cs = 0.f;
    for (int i = t; i < N; i += 256) cs += g_con[i];
    s[t] = cs;
    __syncthreads();
    for (int off = 128; off > 0; off >>= 1) {
        if (t < off) s[t] += s[t + off];
        __syncthreads();
    }
    __shared__ float con_sum;
    if (t == 0) con_sum = s[0];
    __syncthreads();

    s[t] = (t < 32) ? g_ce_part[t] : 0.f;
    __syncthreads();
    for (int off = 128; off > 0; off >>= 1) {
        if (t < off) s[t] += s[t + off];
        __syncthreads();
    }
    if (t == 0) {
        float ce_mean = s[0] * (1.0f / N);
        float con_mean = con_sum * (1.0f / N);
        out[0] = ce_mean + ALPHA * con_mean;
        if (out_size > 1) out[1] = ce_mean;
        if (out_size > 2) out[2] = con_mean;
    }
}

// ---------------- launcher ----------------------------------------------------------
extern "C" void kernel_launch(void* const* d_in, const int* in_sizes, int n_in,
                              void* d_out, int out_size) {
    const float* logits = (const float*)d_in[0];
    const float* emb = (const float*)d_in[1];
    const int* tgt = (const int*)d_in[2];
    float* out = (float*)d_out;

    cudaFuncSetAttribute(k_sim_sym, cudaFuncAttributeMaxDynamicSharedMemorySize, SMEM_TOTAL);

    k_norm<<<N, DIM>>>(emb);
    k_clspart<<<32, 256>>>(tgt);
    k_clsfinal<<<CLS, DIM>>>();
    k_ce<<<N / 256, 256>>>(logits, tgt);
    k_sim_sym<<<130, 256, SMEM_TOTAL>>>();
    k_con<<<N / 8, 256>>>(tgt);
    k_final<<<1, 256>>>(out, out_size);
}

// round 5
// speedup vs baseline: 6.9859x; 1.0011x over previous
#include <cuda_runtime.h>
#include <cuda_fp16.h>
#include <math.h>
#include <stdint.h>

#define N 8192
#define CLS 8
#define DIM 256
#define INV_T 14.285714285714286f
#define EXP_SCALE 20.60992915555662f   /* (1/0.07) * log2(e) */
#define ALPHA 0.3f
#define LSM 0.1f
#define NT_ROW 64

// ---------------- scratch ------------------------------------------------------------
__device__ float g_embn[N * DIM];
__device__ __half g_embh[N * DIM];
__device__ float g_clsum_part[32 * CLS * DIM];
__device__ float g_clcnt_part[32 * CLS];
__device__ float g_clsum[CLS * DIM];
__device__ float g_clcnt[CLS];
__device__ float g_Zp[N * NT_ROW];
__device__ float g_con[N];
__device__ float g_ce_part[32];

// ---------------- helpers ------------------------------------------------------------
__device__ __forceinline__ uint32_t smem_u32(const void* p) {
    uint32_t a;
    asm("{ .reg .u64 t; cvta.to.shared.u64 t, %1; cvt.u32.u64 %0, t; }" : "=r"(a) : "l"(p));
    return a;
}
__device__ __forceinline__ float ex2f(float x) {
    float y; asm("ex2.approx.f32 %0, %1;" : "=f"(y) : "f"(x)); return y;
}
__device__ __forceinline__ void cp16(uint32_t dst, const void* src) {
    asm volatile("cp.async.cg.shared.global [%0], [%1], 16;" :: "r"(dst), "l"(src));
}
#define CP_COMMIT() asm volatile("cp.async.commit_group;" ::: "memory")
#define CP_WAIT0()  asm volatile("cp.async.wait_group 0;" ::: "memory")

__device__ __forceinline__ void ldsm4(uint32_t& r0, uint32_t& r1, uint32_t& r2, uint32_t& r3,
                                      uint32_t addr) {
    asm volatile("ldmatrix.sync.aligned.m8n8.x4.shared.b16 {%0,%1,%2,%3}, [%4];"
                 : "=r"(r0), "=r"(r1), "=r"(r2), "=r"(r3) : "r"(addr));
}
// fp16 accumulate: D(f16x2 x2) = A(f16) * B(f16) + C
__device__ __forceinline__ void mma_f16acc(uint32_t& c0, uint32_t& c1, uint32_t a0, uint32_t a1,
                                           uint32_t a2, uint32_t a3, uint32_t b0, uint32_t b1) {
    asm volatile("mma.sync.aligned.m16n8k16.row.col.f16.f16.f16.f16 "
                 "{%0,%1}, {%2,%3,%4,%5}, {%6,%7}, {%0,%1};"
                 : "+r"(c0), "+r"(c1)
                 : "r"(a0), "r"(a1), "r"(a2), "r"(a3), "r"(b0), "r"(b1));
}

// ---------------- 1) normalize + fp16 convert ---------------------------------------
__global__ void k_norm(const float* __restrict__ emb) {
    int row = blockIdx.x;
    int d = threadIdx.x;
    float v = emb[row * DIM + d];
    __shared__ float s[DIM];
    s[d] = v * v;
    __syncthreads();
    for (int off = DIM / 2; off > 0; off >>= 1) {
        if (d < off) s[d] += s[d + off];
        __syncthreads();
    }
    float norm = fmaxf(sqrtf(s[0]), 1e-12f);
    float nv = v / norm;
    g_embn[row * DIM + d] = nv;
    g_embh[row * DIM + d] = __float2half_rn(nv);
}

// ---------------- 2) class sums ------------------------------------------------------
__global__ void k_clspart(const int* __restrict__ tgt) {
    int b = blockIdx.x, d = threadIdx.x;
    int i0 = b * 256;
    __shared__ int st[256];
    st[d] = tgt[i0 + d];
    __syncthreads();
    float a[CLS];
#pragma unroll
    for (int c = 0; c < CLS; c++) a[c] = 0.f;
    for (int k = 0; k < 256; k++) {
        float v = g_embn[(i0 + k) * DIM + d];
        int t = st[k];
#pragma unroll
        for (int c = 0; c < CLS; c++) a[c] += (t == c) ? v : 0.f;
    }
#pragma unroll
    for (int c = 0; c < CLS; c++) g_clsum_part[(b * CLS + c) * DIM + d] = a[c];
    if (d == 0) {
        int cnt[CLS];
#pragma unroll
        for (int c = 0; c < CLS; c++) cnt[c] = 0;
        for (int k = 0; k < 256; k++) {
#pragma unroll
            for (int c = 0; c < CLS; c++) cnt[c] += (st[k] == c);
        }
#pragma unroll
        for (int c = 0; c < CLS; c++) g_clcnt_part[b * CLS + c] = (float)cnt[c];
    }
}

__global__ void k_clsfinal() {
    int c = blockIdx.x, d = threadIdx.x;
    float s = 0.f;
    for (int b = 0; b < 32; b++) s += g_clsum_part[(b * CLS + c) * DIM + d];
    g_clsum[c * DIM + d] = s;
    if (d == 0) {
        float cn = 0.f;
        for (int b = 0; b < 32; b++) cn += g_clcnt_part[b * CLS + c];
        g_clcnt[c] = cn;
    }
}

// ---------------- 3) focal cross-entropy --------------------------------------------
__global__ void k_ce(const float* __restrict__ logits, const int* __restrict__ tgt) {
    int i = blockIdx.x * 256 + threadIdx.x;
    const float4* p = (const float4*)(logits + i * CLS);
    float4 u = p[0], w = p[1];
    float x[CLS] = {u.x, u.y, u.z, u.w, w.x, w.y, w.z, w.w};
    float m = x[0];
#pragma unroll
    for (int j = 1; j < CLS; j++) m = fmaxf(m, x[j]);
    float se = 0.f;
#pragma unroll
    for (int j = 0; j < CLS; j++) se += expf(x[j] - m);
    float lse = m + logf(se);
    int t = tgt[i];
    float nll = lse - x[t];
    float sx = 0.f;
#pragma unroll
    for (int j = 0; j < CLS; j++) sx += x[j];
    float smooth = lse - sx * (1.0f / CLS);
    float ce = (1.0f - LSM) * nll + LSM * smooth;
    float pt = expf(-ce);
    float omp = 1.0f - pt;
    float focal = omp * omp * ce;

    __shared__ float s[256];
    s[threadIdx.x] = focal;
    __syncthreads();
    for (int off = 128; off > 0; off >>= 1) {
        if (threadIdx.x < off) s[threadIdx.x] += s[threadIdx.x + off];
        __syncthreads();
    }
    if (threadIdx.x == 0) g_ce_part[blockIdx.x] = s[0];
}

// ---------------- 4) HOT: symmetric Z via mma.sync fp16-accum -----------------------
#define SA 264
#define A_BYTES (128 * SA * 2)
#define AS_OFF 0
#define BS_OFF(b) (A_BYTES + (b) * A_BYTES)
#define RED_OFF (3 * A_BYTES)
#define SMEM_TOTAL (RED_OFF + 128 * 2 * 4 + 128 * 4 * 4)

__device__ __forceinline__ void load_tile_async(uint32_t sbase, int grow0, int tid) {
    const char* src = (const char*)g_embh + (size_t)grow0 * 512;
#pragma unroll
    for (int i = 0; i < 16; i++) {
        int idx = tid + i * 256;
        int row = idx >> 5, cb = idx & 31;
        cp16(sbase + row * (SA * 2) + cb * 16, src + (size_t)row * 512 + cb * 16);
    }
}

__global__ void __launch_bounds__(256, 1) k_sim_sym() {
    extern __shared__ char smem[];
    uint32_t sb = smem_u32(smem);
    float* red_row = (float*)(smem + RED_OFF);          // [128][2]
    float* red_col = (float*)(smem + RED_OFF + 1024);   // [128][4]
    int tid = threadIdx.x;
    int lane = tid & 31;
    int wid = tid >> 5;
    int wx = wid & 1;
    int wy = wid >> 1;

    int rem = blockIdx.x * 16;
    int I = 0;
    while (rem >= NT_ROW - I) { rem -= NT_ROW - I; I++; }
    int J = I + rem;

    uint32_t a_addr = sb + AS_OFF + (wy * 32 + (lane & 15)) * (SA * 2) + ((lane >> 4) << 4);
    uint32_t b_addr = sb + ((lane & 7) + ((lane >> 4) << 3)) * (SA * 2) + (((lane >> 3) & 1) << 4);
    uint32_t b_base = b_addr + (wx * 64) * (SA * 2);

    const float EXP_DIAG = expf(INV_T);
    int lrl0 = wy * 32 + (lane >> 2);
    int lcb0 = wx * 64 + (lane & 3) * 2;

    int curI = -1;

    for (int k = 0; k < 16; k++) {
        int buf = k & 1;
        if (I != curI) {
            load_tile_async(sb + AS_OFF, I * 128, tid);
            if (k == 0) load_tile_async(sb + BS_OFF(0), J * 128, tid);
            CP_COMMIT();
            CP_WAIT0();
            __syncthreads();
            curI = I;
        }
        int I1 = I, J1 = J + 1;
        if (J1 == NT_ROW) { I1 = I + 1; J1 = I1; }
        if (k + 1 < 16) {
            load_tile_async(sb + BS_OFF(buf ^ 1), J1 * 128, tid);
            CP_COMMIT();
        }

        // ---- MMA: 128x128x256, fp16 accumulate ----
        uint32_t acc[2][8][2];
#pragma unroll
        for (int mt = 0; mt < 2; mt++)
#pragma unroll
            for (int nt = 0; nt < 8; nt++) { acc[mt][nt][0] = 0u; acc[mt][nt][1] = 0u; }

        uint32_t bbuf = b_base + BS_OFF(buf);
#pragma unroll
        for (int ks = 0; ks < 16; ks++) {
            uint32_t koff = ks * 32;
            uint32_t a0[4], a1[4];
            ldsm4(a0[0], a0[1], a0[2], a0[3], a_addr + koff);
            ldsm4(a1[0], a1[1], a1[2], a1[3], a_addr + 16 * (SA * 2) + koff);
            uint32_t bfr[4][4];
#pragma unroll
            for (int p = 0; p < 4; p++)
                ldsm4(bfr[p][0], bfr[p][1], bfr[p][2], bfr[p][3],
                      bbuf + (p * 16) * (SA * 2) + koff);
#pragma unroll
            for (int nt = 0; nt < 8; nt++) {
                uint32_t bb0 = bfr[nt >> 1][(nt & 1) * 2];
                uint32_t bb1 = bfr[nt >> 1][(nt & 1) * 2 + 1];
                mma_f16acc(acc[0][nt][0], acc[0][nt][1], a0[0], a0[1], a0[2], a0[3], bb0, bb1);
                mma_f16acc(acc[1][nt][0], acc[1][nt][1], a1[0], a1[1], a1[2], a1[3], bb0, bb1);
            }
        }

        // ---- epilogue ----
        bool dt = (I == J);
        float ev[2][8][4];
#pragma unroll
        for (int mt = 0; mt < 2; mt++) {
            int lr = lrl0 + mt * 16;
#pragma unroll
            for (int nt = 0; nt < 8; nt++) {
                int lc = lcb0 + nt * 8;
                float2 lo = __half22float2(*(const __half2*)&acc[mt][nt][0]);
                float2 hi = __half22float2(*(const __half2*)&acc[mt][nt][1]);
                ev[mt][nt][0] = (dt && lc == lr)         ? EXP_DIAG : ex2f(lo.x * EXP_SCALE);
                ev[mt][nt][1] = (dt && lc + 1 == lr)     ? EXP_DIAG : ex2f(lo.y * EXP_SCALE);
                ev[mt][nt][2] = (dt && lc == lr + 8)     ? EXP_DIAG : ex2f(hi.x * EXP_SCALE);
                ev[mt][nt][3] = (dt && lc + 1 == lr + 8) ? EXP_DIAG : ex2f(hi.y * EXP_SCALE);
            }
        }

        // row sums
        float rlo[2], rhi[2];
#pragma unroll
        for (int mt = 0; mt < 2; mt++) {
            float sl = 0.f, sh = 0.f;
#pragma unroll
            for (int nt = 0; nt < 8; nt++) {
                sl += ev[mt][nt][0] + ev[mt][nt][1];
                sh += ev[mt][nt][2] + ev[mt][nt][3];
            }
            sl += __shfl_xor_sync(0xFFFFFFFF, sl, 1);
            sl += __shfl_xor_sync(0xFFFFFFFF, sl, 2);
            sh += __shfl_xor_sync(0xFFFFFFFF, sh, 1);
            sh += __shfl_xor_sync(0xFFFFFFFF, sh, 2);
            rlo[mt] = sl; rhi[mt] = sh;
        }

        // col sums
        float cp0[8], cp1[8];
#pragma unroll
        for (int nt = 0; nt < 8; nt++) {
            float c0 = (ev[0][nt][0] + ev[0][nt][2]) + (ev[1][nt][0] + ev[1][nt][2]);
            float c1 = (ev[0][nt][1] + ev[0][nt][3]) + (ev[1][nt][1] + ev[1][nt][3]);
            c0 += __shfl_xor_sync(0xFFFFFFFF, c0, 4);
            c0 += __shfl_xor_sync(0xFFFFFFFF, c0, 8);
            c0 += __shfl_xor_sync(0xFFFFFFFF, c0, 16);
            c1 += __shfl_xor_sync(0xFFFFFFFF, c1, 4);
            c1 += __shfl_xor_sync(0xFFFFFFFF, c1, 8);
            c1 += __shfl_xor_sync(0xFFFFFFFF, c1, 16);
            cp0[nt] = c0; cp1[nt] = c1;
        }

        if ((lane & 3) == 0) {
#pragma unroll
            for (int mt = 0; mt < 2; mt++) {
                int r = wy * 32 + mt * 16 + (lane >> 2);
                red_row[r * 2 + wx] = rlo[mt];
                red_row[(r + 8) * 2 + wx] = rhi[mt];
            }
        }
        if (lane < 4) {
#pragma unroll
            for (int nt = 0; nt < 8; nt++) {
                int c = wx * 64 + nt * 8 + lane * 2;
                red_col[c * 4 + wy] = cp0[nt];
                red_col[(c + 1) * 4 + wy] = cp1[nt];
            }
        }
        __syncthreads();
        if (tid < 128) {
            float rz = red_row[tid * 2] + red_row[tid * 2 + 1];
            g_Zp[(size_t)(I * 128 + tid) * NT_ROW + J] = rz;
            if (!dt) {
                float cz = (red_col[tid * 4] + red_col[tid * 4 + 1]) +
                           (red_col[tid * 4 + 2] + red_col[tid * 4 + 3]);
                g_Zp[(size_t)(J * 128 + tid) * NT_ROW + I] = cz;
            }
        }
        CP_WAIT0();
        __syncthreads();

        I = I1; J = J1;
    }
}

// ---------------- 5) per-row contrastive loss ---------------------------------------
__global__ void k_con(const int* __restrict__ tgt) {
    int w = threadIdx.x >> 5, lane = threadIdx.x & 31;
    int row = blockIdx.x * 8 + w;
    int t = tgt[row];
    float zs = g_Zp[(size_t)row * NT_ROW + lane] + g_Zp[(size_t)row * NT_ROW + lane + 32];
    const float4* e = (const float4*)&g_embn[row * DIM];
    const float4* sc = (const float4*)&g_clsum[t * DIM];
    float dot = 0.f;
#pragma unroll
    for (int k = lane; k < DIM / 4; k += 32) {
        float4 a = e[k], b = sc[k];
        dot += a.x * b.x + a.y * b.y + a.z * b.z + a.w * b.w;
    }
#pragma unroll
    for (int off = 16; off > 0; off >>= 1) {
        dot += __shfl_xor_sync(0xFFFFFFFF, dot, off);
        zs += __shfl_xor_sync(0xFFFFFFFF, zs, off);
    }
    if (lane == 0) {
        float logZ = logf(zs + 1e-8f);
        float npos = g_clcnt[t] - 1.0f;
        float msum = (dot - 1.0f) * INV_T;
        g_con[row] = (npos * logZ - msum) / fmaxf(npos, 1.0f);
    }
}

// ---------------- 6) final reduction -------------------------------------------------
__global__ void k_final(float* __restrict__ out, int out_size) {
    __shared__ float s[256];
    int t = threadIdx.x;

    float cs = 0.f;
    for (int i = t; i < N; i += 256) cs += g_con[i];
    s[t] = cs;
    __syncthreads();
    for (int off = 128; off > 0; off >>= 1) {
        if (t < off) s[t] += s[t + off];
        __syncthreads();
    }
    __shared__ float con_sum;
    if (t == 0) con_sum = s[0];
    __syncthreads();

    s[t] = (t < 32) ? g_ce_part[t] : 0.f;
    __syncthreads();
    for (int off = 128; off > 0; off >>= 1) {
        if (t < off) s[t] += s[t + off];
        __syncthreads();
    }
    if (t == 0) {
        float ce_mean = s[0] * (1.0f / N);
        float con_mean = con_sum * (1.0f / N);
        out[0] = ce_mean + ALPHA * con_mean;
        if (out_size > 1) out[1] = ce_mean;
        if (out_size > 2) out[2] = con_mean;
    }
}

// ---------------- launcher ----------------------------------------------------------
extern "C" void kernel_launch(void* const* d_in, const int* in_sizes, int n_in,
                              void* d_out, int out_size) {
    const float* logits = (const float*)d_in[0];
    const float* emb = (const float*)d_in[1];
    const int* tgt = (const int*)d_in[2];
    float* out = (float*)d_out;

    cudaFuncSetAttribute(k_sim_sym, cudaFuncAttributeMaxDynamicSharedMemorySize, SMEM_TOTAL);

    k_norm<<<N, DIM>>>(emb);
    k_clspart<<<32, 256>>>(tgt);
    k_clsfinal<<<CLS, DIM>>>();
    k_ce<<<N / 256, 256>>>(logits, tgt);
    k_sim_sym<<<130, 256, SMEM_TOTAL>>>();
    k_con<<<N / 8, 256>>>(tgt);
    k_final<<<1, 256>>>(out, out_size);
}